// round 2
// baseline (speedup 1.0000x reference)
#include <cuda_runtime.h>

// Depthwise 3x3 conv with one-hot (hard-softmax) weight == pure spatial shift:
//   out[b,c,h,w] = x[b,c,h+dh,w+dw]  (zero outside), (dh,dw) from abs-argmax
// of the 9 weights (first max wins, matching jnp.argmax).
// Shapes fixed: B=16, C=64, H=256, W=256 fp32. Single fused kernel:
// each block derives (dh,dw) itself (9 loads, L2-hit after wave 1) -> no
// dependent 1-thread launch. Each thread moves 64B (4x float4) for MLP.

#define H_DIM 256
#define W_DIM 256

__global__ void __launch_bounds__(256)
shift_fused_kernel(const float* __restrict__ x, const float* __restrict__ wt,
                   float* __restrict__ out) {
    __shared__ int s_dh, s_dw;
    if (threadIdx.x == 0) {
        float best = -1.0f;
        int bi = 0;
#pragma unroll
        for (int i = 0; i < 9; ++i) {
            float a = fabsf(__ldg(wt + i));
            if (a > best) { best = a; bi = i; }  // strict > : first max wins
        }
        s_dh = bi / 3 - 1;
        s_dw = bi % 3 - 1;
    }
    __syncthreads();
    const int dh = s_dh;
    const int dw = s_dw;

    // Each thread handles 4 consecutive float4 = 16 floats = 1/16 of a row.
    const long long u = (long long)blockIdx.x * blockDim.x + threadIdx.x;
    const int ur = (int)(u & 15);          // 16 threads per row
    const int h  = (int)((u >> 4) & 255);  // row
    const int bc = (int)(u >> 12);         // b*C + c

    float4 o0 = make_float4(0.f, 0.f, 0.f, 0.f);
    float4 o1 = o0, o2 = o0, o3 = o0;

    const int hi = h + dh;
    if ((unsigned)hi < (unsigned)H_DIM) {
        const float* __restrict__ row = x + ((long long)bc * H_DIM + hi) * W_DIM;
        const int e0 = ur * 16 + dw;  // first input column needed

        if (dw == 0) {
            const float4* __restrict__ r4 =
                reinterpret_cast<const float4*>(row) + ur * 4;
            o0 = __ldg(r4 + 0);
            o1 = __ldg(r4 + 1);
            o2 = __ldg(r4 + 2);
            o3 = __ldg(r4 + 3);
        } else if (e0 >= 0 && e0 + 15 < W_DIM) {
            // Interior thread: 16 unguarded scalar loads, front-batched for MLP.
            const float* __restrict__ p = row + e0;
            float t0 = __ldg(p + 0),  t1 = __ldg(p + 1),  t2 = __ldg(p + 2),  t3 = __ldg(p + 3);
            float t4 = __ldg(p + 4),  t5 = __ldg(p + 5),  t6 = __ldg(p + 6),  t7 = __ldg(p + 7);
            float t8 = __ldg(p + 8),  t9 = __ldg(p + 9),  ta = __ldg(p + 10), tb = __ldg(p + 11);
            float tc = __ldg(p + 12), td = __ldg(p + 13), te = __ldg(p + 14), tf = __ldg(p + 15);
            o0 = make_float4(t0, t1, t2, t3);
            o1 = make_float4(t4, t5, t6, t7);
            o2 = make_float4(t8, t9, ta, tb);
            o3 = make_float4(tc, td, te, tf);
        } else {
            // Row-edge thread: guarded loads.
            float t[16];
#pragma unroll
            for (int i = 0; i < 16; ++i) {
                const int c = e0 + i;
                t[i] = ((unsigned)c < (unsigned)W_DIM) ? __ldg(row + c) : 0.f;
            }
            o0 = make_float4(t[0],  t[1],  t[2],  t[3]);
            o1 = make_float4(t[4],  t[5],  t[6],  t[7]);
            o2 = make_float4(t[8],  t[9],  t[10], t[11]);
            o3 = make_float4(t[12], t[13], t[14], t[15]);
        }
    }

    float4* __restrict__ o4 = reinterpret_cast<float4*>(out) + (u << 2);
    o4[0] = o0;
    o4[1] = o1;
    o4[2] = o2;
    o4[3] = o3;
}

extern "C" void kernel_launch(void* const* d_in, const int* in_sizes, int n_in,
                              void* d_out, int out_size) {
    const float* x  = (const float*)d_in[0];
    const float* wt = (const float*)d_in[1];
    float* out = (float*)d_out;

    // Total float4 units = out_size/4; each thread writes 4 of them.
    const long long n_threads = (long long)out_size >> 4;  // 4,194,304
    const int threads = 256;
    const int blocks = (int)((n_threads + threads - 1) / threads);  // 16384
    shift_fused_kernel<<<blocks, threads>>>(x, wt, out);
}

// round 3
// speedup vs baseline: 2.0439x; 2.0439x over previous
#include <cuda_runtime.h>

// Depthwise 3x3 conv with one-hot (hard-softmax) weight == pure spatial shift:
//   out[b,c,h,w] = x[b,c,h+dh,w+dw]  (zero outside), (dh,dw) = abs-argmax of
// the 9 weights (first max wins, matching jnp.argmax).
// Shapes fixed: B=16, C=64, H=256, W=256 fp32.
//
// Layout lesson from R2: per-thread work must stay warp-interleaved. Each
// thread writes ONE float4 per stream, and handles 2 streams blockDim apart
// (both fully coalesced) for MLP=2. Argmax fused per-block (9 L2-hit loads).

#define H_DIM 256
#define W_DIM 256

__device__ __forceinline__ float4
load_shifted(const float* __restrict__ x, int v, int dh, int dw) {
    // v = float4 output index. W=256 -> 64 float4/row.
    const int w4 = v & 63;
    const int h  = (v >> 6) & 255;
    const int bc = v >> 14;

    float4 val = make_float4(0.f, 0.f, 0.f, 0.f);
    const int hi = h + dh;
    if ((unsigned)hi < (unsigned)H_DIM) {
        const float* __restrict__ row = x + ((long long)bc * H_DIM + hi) * W_DIM;
        if (dw == 0) {
            val = __ldg(reinterpret_cast<const float4*>(row) + w4);
        } else {
            // Lane addresses stride 16B across the warp -> well coalesced.
            const int wa = (w4 << 2) + dw;
            val.x = ((unsigned)wa       < (unsigned)W_DIM) ? __ldg(row + wa)     : 0.f;
            val.y = ((unsigned)(wa + 1) < (unsigned)W_DIM) ? __ldg(row + wa + 1) : 0.f;
            val.z = ((unsigned)(wa + 2) < (unsigned)W_DIM) ? __ldg(row + wa + 2) : 0.f;
            val.w = ((unsigned)(wa + 3) < (unsigned)W_DIM) ? __ldg(row + wa + 3) : 0.f;
        }
    }
    return val;
}

__global__ void __launch_bounds__(256)
shift_fused2_kernel(const float* __restrict__ x, const float* __restrict__ wt,
                    float* __restrict__ out) {
    __shared__ int s_dh, s_dw;
    if (threadIdx.x == 0) {
        float best = -1.0f;
        int bi = 0;
#pragma unroll
        for (int i = 0; i < 9; ++i) {
            float a = fabsf(__ldg(wt + i));
            if (a > best) { best = a; bi = i; }  // strict > : first max wins
        }
        s_dh = bi / 3 - 1;
        s_dw = bi % 3 - 1;
    }
    __syncthreads();
    const int dh = s_dh;
    const int dw = s_dw;

    // Block covers 512 consecutive float4s; thread t handles t and t+256.
    const int base = blockIdx.x * 512;
    const int v0 = base + threadIdx.x;
    const int v1 = v0 + 256;

    // Two independent load chains (front-batched by the compiler -> MLP 2).
    float4 a = load_shifted(x, v0, dh, dw);
    float4 b = load_shifted(x, v1, dh, dw);

    float4* __restrict__ o4 = reinterpret_cast<float4*>(out);
    o4[v0] = a;
    o4[v1] = b;
}

extern "C" void kernel_launch(void* const* d_in, const int* in_sizes, int n_in,
                              void* d_out, int out_size) {
    const float* x  = (const float*)d_in[0];
    const float* wt = (const float*)d_in[1];
    float* out = (float*)d_out;

    const int n4 = out_size >> 2;          // 16,777,216 float4
    const int blocks = n4 / 512;           // 32768 blocks, 256 threads, 2 f4/thread
    shift_fused2_kernel<<<blocks, 256>>>(x, wt, out);
}